// round 11
// baseline (speedup 1.0000x reference)
#include <cuda_runtime.h>
#include <cuda_fp16.h>
#include <cstdint>
#include <cstddef>

// ---------------- problem constants ----------------
#define T_TOK 1024
#define D_IN  2048
#define O_SL  4096
#define TWO_O 8192
#define QWK   256           // D_IN/8 packed int32 per weight row
#define TM    128
#define TN    256
#define KCH   32
#define NCHUNK 64           // D_IN / KCH
#define NSTAGE 4
#define MAX_TILES 12

// ---------------- smem layout (fp16, XOR-swizzled 64B rows) ----------------
// Row = 32 halves = 64B = four 16B groups; group g of row r stored at g^((r>>1)&3).
#define A_BYTES (TM * 64)              // 8192
#define B_BYTES (TN * 64)              // 16384
#define STAGE_B (A_BYTES + B_BYTES)    // 24576
#define SM_MISC 2048                   // bias(1024) + tok(512) + pad
#define SMEM_TOTAL (SM_MISC + NSTAGE * STAGE_B)   // 100352

// ---------------- device scratch ----------------
__device__ __half d_xp[MAX_TILES * TM * D_IN];  // permuted, padded, fp16 x
__device__ int d_perm[T_TOK];
__device__ int d_permp[MAX_TILES * TM];
__device__ int d_tile_a[MAX_TILES];
__device__ int d_ntiles;

// ---------------- helpers ----------------
__device__ __forceinline__ uint32_t smem_u32(const void* p){
    uint32_t a; asm("{ .reg .u64 t; cvta.to.shared.u64 t, %1; cvt.u32.u64 %0, t; }":"=r"(a):"l"(p)); return a;
}
__device__ __forceinline__ void cp_async16(uint32_t dst, const void* src){
    asm volatile("cp.async.cg.shared.global [%0], [%1], 16;" :: "r"(dst), "l"(src) : "memory");
}
__device__ __forceinline__ void cp_commit(){ asm volatile("cp.async.commit_group;" ::: "memory"); }
template<int N> __device__ __forceinline__ void cp_wait(){ asm volatile("cp.async.wait_group %0;" :: "n"(N) : "memory"); }

__device__ __forceinline__ uint32_t lds_u32(uint32_t a){
    uint32_t v; asm("ld.shared.b32 %0, [%1];" : "=r"(v) : "r"(a)); return v;
}
__device__ __forceinline__ uint32_t h2pack(float a, float b){
    uint32_t r; asm("cvt.rn.f16x2.f32 %0, %1, %2;" : "=r"(r) : "f"(b), "f"(a)); return r;
}
__device__ __forceinline__ void mma_f16(float* d, const uint32_t* a, const uint32_t* b){
    asm("mma.sync.aligned.m16n8k16.row.col.f32.f16.f16.f32 "
        "{%0,%1,%2,%3}, {%4,%5,%6,%7}, {%8,%9}, {%0,%1,%2,%3};"
        : "+f"(d[0]), "+f"(d[1]), "+f"(d[2]), "+f"(d[3])
        : "r"(a[0]), "r"(a[1]), "r"(a[2]), "r"(a[3]), "r"(b[0]), "r"(b[1]));
}

// ---------------------------------------------------------------------------
// Kernel 1: group tokens by adapter into 128-row tiles, build padded perm.
// ---------------------------------------------------------------------------
__global__ void group_tokens_kernel(const int* __restrict__ indices)
{
    __shared__ int cnt[4], off[4], cur[4];
    __shared__ int s_start[MAX_TILES], s_rows[MAX_TILES], s_nt;
    int tid = threadIdx.x;
    if (tid < 4) { cnt[tid] = 0; cur[tid] = 0; }
    __syncthreads();
    for (int t = tid; t < T_TOK; t += blockDim.x) atomicAdd(&cnt[indices[t]], 1);
    __syncthreads();
    if (tid == 0) {
        int o = 0, ntl = 0;
        for (int a = 0; a < 4; a++) {
            off[a] = o;
            for (int r = 0; r < cnt[a]; r += TM) {
                d_tile_a[ntl] = a;
                s_start[ntl]  = o + r;
                s_rows[ntl]   = min(TM, cnt[a] - r);
                ntl++;
            }
            o += cnt[a];
        }
        s_nt = ntl;
        d_ntiles = ntl;
    }
    __syncthreads();
    for (int t = tid; t < T_TOK; t += blockDim.x) {
        int a = indices[t];
        int p = off[a] + atomicAdd(&cur[a], 1);
        d_perm[p] = t;
    }
    __syncthreads();
    for (int idx = tid; idx < MAX_TILES * TM; idx += blockDim.x) {
        int tl = idx >> 7, r = idx & 127;
        int v = -1;
        if (tl < s_nt && r < s_rows[tl]) v = d_perm[s_start[tl] + r];
        d_permp[idx] = v;
    }
}

// ---------------------------------------------------------------------------
// Kernel 2: permuted / padded / fp16 x copy (one block per row)
// ---------------------------------------------------------------------------
__global__ void build_xp_kernel(const float* __restrict__ x)
{
    int p = blockIdx.x;
    int t = d_permp[p];
    uint32_t* dst = reinterpret_cast<uint32_t*>(d_xp + (size_t)p * D_IN);
    if (t >= 0) {
        const float4* src = reinterpret_cast<const float4*>(x + (size_t)t * D_IN);
#pragma unroll
        for (int it = 0; it < 2; it++) {
            int j = threadIdx.x + it * 256;
            float4 v = src[j];
            dst[2 * j + 0] = h2pack(v.x, v.y);
            dst[2 * j + 1] = h2pack(v.z, v.w);
        }
    } else {
#pragma unroll
        for (int it = 0; it < 2; it++) {
            int j = threadIdx.x + it * 256;
            dst[2 * j + 0] = 0u;
            dst[2 * j + 1] = 0u;
        }
    }
}

// ---------------------------------------------------------------------------
// Kernel 3: mma.sync fp16 fused GEMM. Block = 128(M) x 256(N), 8 warps 2x4,
// warp tile 64x64, K-chunk 32 (2 k16 steps), 4-stage cp.async pipeline.
// ---------------------------------------------------------------------------
__global__ void __launch_bounds__(256, 1)
fused_mma_kernel(const float* __restrict__ Wb,
                 const float* __restrict__ bias,
                 const int*   __restrict__ qw0,
                 const int*   __restrict__ qw1,
                 const int*   __restrict__ qz0,
                 const int*   __restrict__ qz1,
                 const float* __restrict__ sc0,
                 const float* __restrict__ sc1,
                 float*       __restrict__ out)
{
    const int mt = blockIdx.y;
    if (mt >= d_ntiles) return;

    extern __shared__ char smem[];
    const uint32_t smb = smem_u32(smem);
    const int tid  = threadIdx.x;
    const int wid  = tid >> 5;
    const int lane = tid & 31;

    const int a  = d_tile_a[mt];
    const int n0 = blockIdx.x * TN;
    const int sl = (n0 >= O_SL);
    const int ob = n0 & (O_SL - 1);

    const int*   qw = (sl ? qw1 : qw0) + (size_t)a * O_SL * QWK;
    const int*   qz = (sl ? qz1 : qz0) + a * (O_SL / 8);
    const float* sc = (sl ? sc1 : sc0) + a * O_SL;

    // misc smem: bias[256] at 0, tok[128] at 1024
    {
        float* s_bias = reinterpret_cast<float*>(smem);
        s_bias[tid] = bias[n0 + tid];
        if (tid < TM) reinterpret_cast<int*>(smem + 1024)[tid] = d_permp[mt * TM + tid];
    }

    // -------- per-thread B producer metadata: one output row per thread ------
    const int   orow = ob + tid;                  // row within slice
    const float s_   = __ldg(sc + orow);
    const float zf   = s_ * (float)((__ldg(&qz[orow >> 3]) >> ((orow & 7) * 4)) & 0xF);
    const float* wp  = Wb + (size_t)(n0 + tid) * D_IN;
    const int*   qp  = qw + (size_t)orow * QWK;
    const uint32_t bkey = (uint32_t)((tid >> 1) & 3);      // 16B-group XOR key
    const uint32_t b_row_sts = (uint32_t)(tid * 64);

    const __half* xpt = d_xp + (size_t)mt * TM * D_IN;

#define LDG_B(c, WBR, QR) do {                                                 \
        const int k0 = (c) * KCH;                                              \
        _Pragma("unroll")                                                      \
        for (int i = 0; i < 8; i++)                                            \
            (WBR)[i] = *reinterpret_cast<const float4*>(wp + k0 + i * 4);      \
        _Pragma("unroll")                                                      \
        for (int i = 0; i < 4; i++)                                            \
            (QR)[i] = __ldg(qp + (k0 >> 3) + i);                               \
    } while (0)

#define STS_B(c, WBR, QR) do {                                                 \
        const uint32_t bb = smb + SM_MISC + ((c) % NSTAGE) * STAGE_B + A_BYTES \
                          + b_row_sts;                                         \
        _Pragma("unroll")                                                      \
        for (int gi = 0; gi < 4; gi++) {                                       \
            int   q  = (QR)[gi];                                               \
            float4 wa = (WBR)[2 * gi + 0];                                     \
            float4 wbv = (WBR)[2 * gi + 1];                                    \
            uint32_t h0 = h2pack(wa.x  + s_ * (float)((q >> 0)  & 0xF) - zf,   \
                                 wa.y  + s_ * (float)((q >> 4)  & 0xF) - zf);  \
            uint32_t h1 = h2pack(wa.z  + s_ * (float)((q >> 8)  & 0xF) - zf,   \
                                 wa.w  + s_ * (float)((q >> 12) & 0xF) - zf);  \
            uint32_t h2 = h2pack(wbv.x + s_ * (float)((q >> 16) & 0xF) - zf,   \
                                 wbv.y + s_ * (float)((q >> 20) & 0xF) - zf);  \
            uint32_t h3 = h2pack(wbv.z + s_ * (float)((q >> 24) & 0xF) - zf,   \
                                 wbv.w + s_ * (float)(((uint32_t)q >> 28) & 0xF) - zf); \
            asm volatile("st.shared.v4.b32 [%0], {%1,%2,%3,%4};"               \
                :: "r"(bb + (((uint32_t)gi ^ bkey) << 4)),                     \
                   "r"(h0), "r"(h1), "r"(h2), "r"(h3) : "memory");             \
        }                                                                      \
    } while (0)

#define CPA_A(c) do {                                                          \
        const uint32_t ab = smb + SM_MISC + ((c) % NSTAGE) * STAGE_B;          \
        const int k0 = (c) * KCH;                                              \
        _Pragma("unroll")                                                      \
        for (int j = 0; j < 2; j++) {                                          \
            int idx = tid + j * 256;            /* 0..511 */                   \
            int row = idx >> 2, g = idx & 3;                                   \
            cp_async16(ab + (uint32_t)(row * 64 + ((g ^ ((row >> 1) & 3)) * 16)), \
                       xpt + (size_t)row * D_IN + k0 + g * 8);                 \
        }                                                                      \
    } while (0)

    // -------- prologue: fill stages 0..2 --------
    {
        float4 wbr[8]; int qr[4];
#pragma unroll
        for (int p = 0; p < 3; p++) {
            LDG_B(p, wbr, qr);
            STS_B(p, wbr, qr);
            CPA_A(p);
            cp_commit();
        }
    }

    // -------- accumulators --------
    float acc[4][8][4];
#pragma unroll
    for (int mf = 0; mf < 4; mf++)
#pragma unroll
        for (int nf = 0; nf < 8; nf++)
#pragma unroll
            for (int e = 0; e < 4; e++) acc[mf][nf][e] = 0.0f;

    const int wr = wid >> 2;      // 0..1 (M)
    const int wc = wid & 3;       // 0..3 (N)
    const int qd = lane >> 2;     // quad row 0..7
    const int jj = lane & 3;      // k quarter
    const uint32_t qk = (uint32_t)((qd >> 1) & 3);   // XOR key for this lane's rows
    // group-offset tables per k16 step: group (2ks+h)^qk, plus word jj
    const uint32_t goff[2][2] = {
        { ((0u ^ qk) << 4) + (uint32_t)jj * 4, ((1u ^ qk) << 4) + (uint32_t)jj * 4 },
        { ((2u ^ qk) << 4) + (uint32_t)jj * 4, ((3u ^ qk) << 4) + (uint32_t)jj * 4 }
    };
    const uint32_t a_row = (uint32_t)((wr * 64 + qd) * 64);
    const uint32_t b_row = (uint32_t)(A_BYTES + (wc * 64 + qd) * 64);

    // -------- main loop --------
    for (int c = 0; c < NCHUNK; c++) {
        cp_wait<2>();
        __syncthreads();

        float4 wbr[8]; int qr[4];
        const bool pf = (c + 3 < NCHUNK);
        if (pf) LDG_B(c + 3, wbr, qr);

        const uint32_t stage = smb + SM_MISC + (c % NSTAGE) * STAGE_B;
#pragma unroll
        for (int ks = 0; ks < 2; ks++) {
            const uint32_t g0 = goff[ks][0];
            const uint32_t g1 = goff[ks][1];
            uint32_t Af[4][4];
#pragma unroll
            for (int mf = 0; mf < 4; mf++) {
                uint32_t base = stage + a_row + mf * 1024;   // 16 rows * 64B
                Af[mf][0] = lds_u32(base + g0);
                Af[mf][1] = lds_u32(base + 512 + g0);        // +8 rows
                Af[mf][2] = lds_u32(base + g1);
                Af[mf][3] = lds_u32(base + 512 + g1);
            }
            uint32_t Bf[8][2];
#pragma unroll
            for (int nf = 0; nf < 8; nf++) {
                uint32_t base = stage + b_row + nf * 512;    // 8 rows * 64B
                Bf[nf][0] = lds_u32(base + g0);
                Bf[nf][1] = lds_u32(base + g1);
            }
#pragma unroll
            for (int mf = 0; mf < 4; mf++)
#pragma unroll
                for (int nf = 0; nf < 8; nf++)
                    mma_f16(acc[mf][nf], Af[mf], Bf[nf]);
        }

        if (pf) { STS_B(c + 3, wbr, qr); CPA_A(c + 3); }
        cp_commit();
    }

    // -------- epilogue --------
    __syncthreads();
    {
        const float* s_bias = reinterpret_cast<const float*>(smem);
        const int*   s_tok  = reinterpret_cast<const int*>(smem + 1024);
#pragma unroll
        for (int mf = 0; mf < 4; mf++) {
            int r_lo = wr * 64 + mf * 16 + qd;
            int t_lo = s_tok[r_lo];
            int t_hi = s_tok[r_lo + 8];
#pragma unroll
            for (int nf = 0; nf < 8; nf++) {
                int ncol = n0 + wc * 64 + nf * 8 + 2 * jj;
                float b0 = s_bias[ncol - n0];
                float b1 = s_bias[ncol - n0 + 1];
                if (t_lo >= 0) {
                    float2 v = make_float2(acc[mf][nf][0] + b0, acc[mf][nf][1] + b1);
                    *reinterpret_cast<float2*>(out + (size_t)t_lo * TWO_O + ncol) = v;
                }
                if (t_hi >= 0) {
                    float2 v = make_float2(acc[mf][nf][2] + b0, acc[mf][nf][3] + b1);
                    *reinterpret_cast<float2*>(out + (size_t)t_hi * TWO_O + ncol) = v;
                }
            }
        }
    }
#undef STS_B
#undef CPA_A
#undef LDG_B
}

// ---------------------------------------------------------------------------
extern "C" void kernel_launch(void* const* d_in, const int* in_sizes, int n_in,
                              void* d_out, int out_size)
{
    const float* x    = (const float*)d_in[0];
    const float* Wb   = (const float*)d_in[1];
    const float* bias = (const float*)d_in[2];
    const int*   qw0  = (const int*)d_in[3];
    const int*   qw1  = (const int*)d_in[4];
    const int*   qz0  = (const int*)d_in[5];
    const int*   qz1  = (const int*)d_in[6];
    const float* sc0  = (const float*)d_in[7];
    const float* sc1  = (const float*)d_in[8];
    const int* indices = (const int*)d_in[11];
    float* out = (float*)d_out;

    static int configured = 0;
    if (!configured) {
        cudaFuncSetAttribute(fused_mma_kernel,
                             cudaFuncAttributeMaxDynamicSharedMemorySize, SMEM_TOTAL);
        configured = 1;
    }

    group_tokens_kernel<<<1, 256>>>(indices);
    build_xp_kernel<<<MAX_TILES * TM, 256>>>(x);
    fused_mma_kernel<<<dim3(TWO_O / TN, MAX_TILES), 256, SMEM_TOTAL>>>(
        Wb, bias, qw0, qw1, qz0, qz1, sc0, sc1, out);
}

// round 12
// speedup vs baseline: 1.3099x; 1.3099x over previous
#include <cuda_runtime.h>
#include <cuda_fp16.h>
#include <cstdint>
#include <cstddef>

// ---------------- problem constants ----------------
#define T_TOK 1024
#define D_IN  2048
#define O_SL  4096
#define TWO_O 8192
#define QWK   256           // D_IN/8 packed int32 per weight row
#define TM    128
#define TN    128
#define KCH   64            // fp32 K per chunk (=128B fp16 row)
#define NCHUNK 32           // D_IN / KCH
#define NSTAGE 3
#define MAX_TILES 12

// ---------------- smem layout (fp16, XOR-swizzled 128B rows) ----------------
// Row = 64 halves = 128B = eight 16B groups; group g of row r stored at g^(r&7).
#define A_BYTES (TM * 128)             // 16384
#define B_BYTES (TN * 128)             // 16384
#define STAGE_B (A_BYTES + B_BYTES)    // 32768
#define SM_MISC 2048                   // bias(512) + tok(512) + pad
#define SMEM_TOTAL (SM_MISC + NSTAGE * STAGE_B)   // 100352 -> 2 CTAs/SM

// ---------------- device scratch ----------------
__device__ __half d_xp[MAX_TILES * TM * D_IN];  // permuted, padded, fp16 x
__device__ int d_perm[T_TOK];
__device__ int d_permp[MAX_TILES * TM];
__device__ int d_tile_a[MAX_TILES];
__device__ int d_ntiles;

// ---------------- helpers ----------------
__device__ __forceinline__ uint32_t smem_u32(const void* p){
    uint32_t a; asm("{ .reg .u64 t; cvta.to.shared.u64 t, %1; cvt.u32.u64 %0, t; }":"=r"(a):"l"(p)); return a;
}
__device__ __forceinline__ void cp_async16(uint32_t dst, const void* src){
    asm volatile("cp.async.cg.shared.global [%0], [%1], 16;" :: "r"(dst), "l"(src) : "memory");
}
__device__ __forceinline__ void cp_commit(){ asm volatile("cp.async.commit_group;" ::: "memory"); }
template<int N> __device__ __forceinline__ void cp_wait(){ asm volatile("cp.async.wait_group %0;" :: "n"(N) : "memory"); }

__device__ __forceinline__ uint32_t lds_u32(uint32_t a){
    uint32_t v; asm("ld.shared.b32 %0, [%1];" : "=r"(v) : "r"(a)); return v;
}
__device__ __forceinline__ uint32_t h2pack(float a, float b){
    uint32_t r; asm("cvt.rn.f16x2.f32 %0, %1, %2;" : "=r"(r) : "f"(b), "f"(a)); return r;
}
__device__ __forceinline__ void mma_f16(float* d, const uint32_t* a, const uint32_t* b){
    asm("mma.sync.aligned.m16n8k16.row.col.f32.f16.f16.f32 "
        "{%0,%1,%2,%3}, {%4,%5,%6,%7}, {%8,%9}, {%0,%1,%2,%3};"
        : "+f"(d[0]), "+f"(d[1]), "+f"(d[2]), "+f"(d[3])
        : "r"(a[0]), "r"(a[1]), "r"(a[2]), "r"(a[3]), "r"(b[0]), "r"(b[1]));
}

// ---------------------------------------------------------------------------
// Kernel 1: group tokens by adapter into 128-row tiles, build padded perm.
// ---------------------------------------------------------------------------
__global__ void group_tokens_kernel(const int* __restrict__ indices)
{
    __shared__ int cnt[4], off[4], cur[4];
    __shared__ int s_start[MAX_TILES], s_rows[MAX_TILES], s_nt;
    int tid = threadIdx.x;
    if (tid < 4) { cnt[tid] = 0; cur[tid] = 0; }
    __syncthreads();
    for (int t = tid; t < T_TOK; t += blockDim.x) atomicAdd(&cnt[indices[t]], 1);
    __syncthreads();
    if (tid == 0) {
        int o = 0, ntl = 0;
        for (int a = 0; a < 4; a++) {
            off[a] = o;
            for (int r = 0; r < cnt[a]; r += TM) {
                d_tile_a[ntl] = a;
                s_start[ntl]  = o + r;
                s_rows[ntl]   = min(TM, cnt[a] - r);
                ntl++;
            }
            o += cnt[a];
        }
        s_nt = ntl;
        d_ntiles = ntl;
    }
    __syncthreads();
    for (int t = tid; t < T_TOK; t += blockDim.x) {
        int a = indices[t];
        int p = off[a] + atomicAdd(&cur[a], 1);
        d_perm[p] = t;
    }
    __syncthreads();
    for (int idx = tid; idx < MAX_TILES * TM; idx += blockDim.x) {
        int tl = idx >> 7, r = idx & 127;
        int v = -1;
        if (tl < s_nt && r < s_rows[tl]) v = d_perm[s_start[tl] + r];
        d_permp[idx] = v;
    }
}

// ---------------------------------------------------------------------------
// Kernel 2: permuted / padded / fp16 x copy (one block per row)
// ---------------------------------------------------------------------------
__global__ void build_xp_kernel(const float* __restrict__ x)
{
    int p = blockIdx.x;
    int t = d_permp[p];
    uint32_t* dst = reinterpret_cast<uint32_t*>(d_xp + (size_t)p * D_IN);
    if (t >= 0) {
        const float4* src = reinterpret_cast<const float4*>(x + (size_t)t * D_IN);
#pragma unroll
        for (int it = 0; it < 2; it++) {
            int j = threadIdx.x + it * 256;
            float4 v = src[j];
            dst[2 * j + 0] = h2pack(v.x, v.y);
            dst[2 * j + 1] = h2pack(v.z, v.w);
        }
    } else {
#pragma unroll
        for (int it = 0; it < 2; it++) {
            int j = threadIdx.x + it * 256;
            dst[2 * j + 0] = 0u;
            dst[2 * j + 1] = 0u;
        }
    }
}

// ---------------------------------------------------------------------------
// Kernel 3: fp16 mma.sync fused GEMM. Block = 128(M) x 128(N), 8 warps 4x2,
// warp tile 32x64, K-chunk 64 (4 k16 steps), 3-stage cp.async, occ 2.
// B producer: 2 threads/row, two quarter-passes interleaved with MMA k-steps.
// ---------------------------------------------------------------------------
__global__ void __launch_bounds__(256, 2)
fused_mma_kernel(const float* __restrict__ Wb,
                 const float* __restrict__ bias,
                 const int*   __restrict__ qw0,
                 const int*   __restrict__ qw1,
                 const int*   __restrict__ qz0,
                 const int*   __restrict__ qz1,
                 const float* __restrict__ sc0,
                 const float* __restrict__ sc1,
                 float*       __restrict__ out)
{
    const int mt = blockIdx.y;
    if (mt >= d_ntiles) return;

    extern __shared__ char smem[];
    const uint32_t smb = smem_u32(smem);
    const int tid  = threadIdx.x;
    const int wid  = tid >> 5;
    const int lane = tid & 31;

    const int a  = d_tile_a[mt];
    const int n0 = blockIdx.x * TN;
    const int sl = (n0 >= O_SL);
    const int ob = n0 & (O_SL - 1);

    const int*   qw = (sl ? qw1 : qw0) + (size_t)a * O_SL * QWK;
    const int*   qz = (sl ? qz1 : qz0) + a * (O_SL / 8);
    const float* sc = (sl ? sc1 : sc0) + a * O_SL;

    // misc smem: bias[128] at 0, tok[128] at 512
    if (tid < TN) reinterpret_cast<float*>(smem)[tid] = bias[n0 + tid];
    if (tid >= 128) reinterpret_cast<int*>(smem + 512)[tid - 128] = d_permp[mt * TM + tid - 128];

    // -------- B producer metadata: 2 threads per output row ------
    const int   brow = tid >> 1;                 // 0..127
    const int   bhh  = tid & 1;                  // which half (quarters 2h,2h+1)
    const int   orow = ob + brow;
    const float s_   = __ldg(sc + orow);
    const float zf   = s_ * (float)((__ldg(&qz[orow >> 3]) >> ((orow & 7) * 4)) & 0xF);
    const float* wp  = Wb + (size_t)(n0 + brow) * D_IN;
    const int*   qp  = qw + (size_t)orow * QWK;
    const uint32_t bkey = (uint32_t)(brow & 7);
    const uint32_t b_row_sts = (uint32_t)(A_BYTES + brow * 128);

    const __half* xpt = d_xp + (size_t)mt * TM * D_IN;

// quarter qtr covers fp32 k [16*qtr, 16*qtr+16) of the chunk
#define LDG_BQ(c, qi, W4, QQ) do {                                             \
        const int qtr = bhh * 2 + (qi);                                        \
        const int kf  = (c) * KCH + qtr * 16;                                  \
        _Pragma("unroll")                                                      \
        for (int i = 0; i < 4; i++)                                            \
            (W4)[i] = *reinterpret_cast<const float4*>(wp + kf + i * 4);       \
        (QQ)[0] = __ldg(qp + (kf >> 3));                                       \
        (QQ)[1] = __ldg(qp + (kf >> 3) + 1);                                   \
    } while (0)

#define STS_BQ(c, qi, W4, QQ) do {                                             \
        const int qtr = bhh * 2 + (qi);                                        \
        const uint32_t bb = smb + SM_MISC + ((c) % NSTAGE) * STAGE_B + b_row_sts; \
        _Pragma("unroll")                                                      \
        for (int u = 0; u < 2; u++) {                                          \
            int q = (QQ)[u];                                                   \
            float4 wa = (W4)[2 * u + 0];                                       \
            float4 wb = (W4)[2 * u + 1];                                       \
            uint32_t h0 = h2pack(wa.x + s_ * (float)((q >> 0)  & 0xF) - zf,    \
                                 wa.y + s_ * (float)((q >> 4)  & 0xF) - zf);   \
            uint32_t h1 = h2pack(wa.z + s_ * (float)((q >> 8)  & 0xF) - zf,    \
                                 wa.w + s_ * (float)((q >> 12) & 0xF) - zf);   \
            uint32_t h2 = h2pack(wb.x + s_ * (float)((q >> 16) & 0xF) - zf,    \
                                 wb.y + s_ * (float)((q >> 20) & 0xF) - zf);   \
            uint32_t h3 = h2pack(wb.z + s_ * (float)((q >> 24) & 0xF) - zf,    \
                                 wb.w + s_ * (float)(((uint32_t)q >> 28) & 0xF) - zf); \
            uint32_t g  = ((uint32_t)(2 * qtr + u) ^ bkey) << 4;               \
            asm volatile("st.shared.v4.b32 [%0], {%1,%2,%3,%4};"               \
                :: "r"(bb + g), "r"(h0), "r"(h1), "r"(h2), "r"(h3) : "memory"); \
        }                                                                      \
    } while (0)

#define CPA_A(c) do {                                                          \
        const uint32_t ab = smb + SM_MISC + ((c) % NSTAGE) * STAGE_B;          \
        const int k0 = (c) * KCH;                                              \
        _Pragma("unroll")                                                      \
        for (int j = 0; j < 4; j++) {                                          \
            int idx = tid + j * 256;            /* 0..1023 */                  \
            int row = idx >> 3, g = idx & 7;                                   \
            cp_async16(ab + (uint32_t)(row * 128 + ((g ^ (row & 7)) * 16)),    \
                       xpt + (size_t)row * D_IN + k0 + g * 8);                 \
        }                                                                      \
    } while (0)

    // -------- prologue: fill stages for chunks 0,1 --------
    {
        float4 w4[4]; int qq[2];
#pragma unroll
        for (int p = 0; p < 2; p++) {
            LDG_BQ(p, 0, w4, qq);
            STS_BQ(p, 0, w4, qq);
            LDG_BQ(p, 1, w4, qq);
            STS_BQ(p, 1, w4, qq);
            CPA_A(p);
            cp_commit();
        }
    }

    // -------- accumulators --------
    float acc[2][8][4];
#pragma unroll
    for (int mf = 0; mf < 2; mf++)
#pragma unroll
        for (int nf = 0; nf < 8; nf++)
#pragma unroll
            for (int e = 0; e < 4; e++) acc[mf][nf][e] = 0.0f;

    const int wr = wid >> 1;      // 0..3 (M): rows wr*32 + mf*16
    const int wc = wid & 1;       // 0..1 (N): cols wc*64
    const int qd = lane >> 2;     // quad row 0..7 (= XOR key for all frag rows)
    const int jj = lane & 3;      // k word
    const uint32_t a_base = (uint32_t)((wr * 32 + qd) * 128 + jj * 4);
    const uint32_t b_base = (uint32_t)(A_BYTES + (wc * 64 + qd) * 128 + jj * 4);

    // -------- main loop --------
    for (int c = 0; c < NCHUNK; c++) {
        cp_wait<1>();
        __syncthreads();

        const bool pf = (c + 2 < NCHUNK);
        float4 w4[4]; int qq[2];
        if (pf) LDG_BQ(c + 2, 0, w4, qq);

        const uint32_t stage = smb + SM_MISC + (c % NSTAGE) * STAGE_B;

#pragma unroll
        for (int half = 0; half < 2; half++) {
#pragma unroll
            for (int ks2 = 0; ks2 < 2; ks2++) {
                const int ks = half * 2 + ks2;
                const uint32_t g0 = (uint32_t)(((2 * ks + 0) ^ qd) * 16);
                const uint32_t g1 = (uint32_t)(((2 * ks + 1) ^ qd) * 16);
                uint32_t Af[2][4];
#pragma unroll
                for (int mf = 0; mf < 2; mf++) {
                    uint32_t base = stage + a_base + mf * 2048;   // 16 rows*128B
                    Af[mf][0] = lds_u32(base + g0);
                    Af[mf][1] = lds_u32(base + 1024 + g0);        // +8 rows
                    Af[mf][2] = lds_u32(base + g1);
                    Af[mf][3] = lds_u32(base + 1024 + g1);
                }
#pragma unroll
                for (int nf = 0; nf < 8; nf++) {
                    uint32_t base = stage + b_base + nf * 1024;   // 8 rows*128B
                    uint32_t Bf[2];
                    Bf[0] = lds_u32(base + g0);
                    Bf[1] = lds_u32(base + g1);
#pragma unroll
                    for (int mf = 0; mf < 2; mf++)
                        mma_f16(acc[mf][nf], Af[mf], Bf);
                }
            }
            // interleave producer work between the two MMA halves
            if (pf) {
                if (half == 0) {
                    STS_BQ(c + 2, 0, w4, qq);
                    LDG_BQ(c + 2, 1, w4, qq);
                } else {
                    STS_BQ(c + 2, 1, w4, qq);
                    CPA_A(c + 2);
                }
            }
        }
        cp_commit();
    }

    // -------- epilogue --------
    __syncthreads();
    {
        const float* s_bias = reinterpret_cast<const float*>(smem);
        const int*   s_tok  = reinterpret_cast<const int*>(smem + 512);
#pragma unroll
        for (int mf = 0; mf < 2; mf++) {
            int r_lo = wr * 32 + mf * 16 + qd;
            int t_lo = s_tok[r_lo];
            int t_hi = s_tok[r_lo + 8];
#pragma unroll
            for (int nf = 0; nf < 8; nf++) {
                int nloc = wc * 64 + nf * 8 + 2 * jj;
                float b0 = s_bias[nloc];
                float b1 = s_bias[nloc + 1];
                if (t_lo >= 0) {
                    float2 v = make_float2(acc[mf][nf][0] + b0, acc[mf][nf][1] + b1);
                    *reinterpret_cast<float2*>(out + (size_t)t_lo * TWO_O + n0 + nloc) = v;
                }
                if (t_hi >= 0) {
                    float2 v = make_float2(acc[mf][nf][2] + b0, acc[mf][nf][3] + b1);
                    *reinterpret_cast<float2*>(out + (size_t)t_hi * TWO_O + n0 + nloc) = v;
                }
            }
        }
    }
#undef STS_BQ
#undef LDG_BQ
#undef CPA_A
}

// ---------------------------------------------------------------------------
extern "C" void kernel_launch(void* const* d_in, const int* in_sizes, int n_in,
                              void* d_out, int out_size)
{
    const float* x    = (const float*)d_in[0];
    const float* Wb   = (const float*)d_in[1];
    const float* bias = (const float*)d_in[2];
    const int*   qw0  = (const int*)d_in[3];
    const int*   qw1  = (const int*)d_in[4];
    const int*   qz0  = (const int*)d_in[5];
    const int*   qz1  = (const int*)d_in[6];
    const float* sc0  = (const float*)d_in[7];
    const float* sc1  = (const float*)d_in[8];
    const int* indices = (const int*)d_in[11];
    float* out = (float*)d_out;

    static int configured = 0;
    if (!configured) {
        cudaFuncSetAttribute(fused_mma_kernel,
                             cudaFuncAttributeMaxDynamicSharedMemorySize, SMEM_TOTAL);
        configured = 1;
    }

    group_tokens_kernel<<<1, 256>>>(indices);
    build_xp_kernel<<<MAX_TILES * TM, 256>>>(x);
    fused_mma_kernel<<<dim3(TWO_O / TN, MAX_TILES), 256, SMEM_TOTAL>>>(
        Wb, bias, qw0, qw1, qz0, qz1, sc0, sc1, out);
}